// round 5
// baseline (speedup 1.0000x reference)
#include <cuda_runtime.h>
#include <cuda_bf16.h>

#define Bb   64
#define Nn   1024
#define G3H  768

// smem float offsets for scan kernel
#define HS_F  24960            // W slice: 96 rows * 260 floats (pitch 65 float4)
#define GH_F  27040            // h buffers: 2 * 4 * 260
#define GI_F  27424            // gh staging: 96*4
#define SMEMB ((27424 + 768) * 4)   // + gi double buffer 2*384  => 112768 B

// Precomputed input-gate tables (allocation-free scratch)
__device__ float g_TE[300 * G3H];    // type_emb @ w_ih^T
__device__ float g_POS[1000 * G3H];  // pos_table @ w_ih^T

// ---------------------------------------------------------------------------
// proj: out[r][j] = dot(A[r, 0:256], W[j, 0:256]);  grid (ceil(rows/8), 6), 128 thr
// ---------------------------------------------------------------------------
__global__ void proj_kernel(const float* __restrict__ A, const float* __restrict__ W,
                            int rows, int which)
{
    __shared__ float As[8][256];
    float* outp = which ? g_POS : g_TE;
    int r0 = blockIdx.x * 8;
    int j  = blockIdx.y * 128 + threadIdx.x;

    for (int idx = threadIdx.x; idx < 2048; idx += 128) {
        int rr = idx >> 8, kk = idx & 255;
        As[rr][kk] = (r0 + rr < rows) ? A[(r0 + rr) * 256 + kk] : 0.f;
    }
    __syncthreads();

    float acc[8] = {0, 0, 0, 0, 0, 0, 0, 0};
    const float4* W4 = (const float4*)W + j * 64;
#pragma unroll 8
    for (int kc = 0; kc < 64; kc++) {
        float4 w = W4[kc];
#pragma unroll
        for (int rr = 0; rr < 8; rr++) {
            acc[rr] = fmaf(w.x, As[rr][kc * 4 + 0], acc[rr]);
            acc[rr] = fmaf(w.y, As[rr][kc * 4 + 1], acc[rr]);
            acc[rr] = fmaf(w.z, As[rr][kc * 4 + 2], acc[rr]);
            acc[rr] = fmaf(w.w, As[rr][kc * 4 + 3], acc[rr]);
        }
    }
#pragma unroll
    for (int rr = 0; rr < 8; rr++)
        if (r0 + rr < rows) outp[(r0 + rr) * G3H + j] = acc[rr];
}

// ---------------------------------------------------------------------------
// embedding half: out[n][b][0:256] = 4*te[t] + 0.25*pos[p] + 2*(tok[v0]+tok[v1])
// grid (256, 64), 256 thr (4 n's per block, 64 float4 lanes each)
// ---------------------------------------------------------------------------
__global__ void embed_kernel(const int* __restrict__ types, const int* __restrict__ vals,
                             const int* __restrict__ cpos,
                             const float* __restrict__ te, const float* __restrict__ pos,
                             const float* __restrict__ tok, float* __restrict__ out)
{
    int sub = threadIdx.x >> 6;
    int t   = threadIdx.x & 63;
    int n   = blockIdx.x * 4 + sub;
    int b   = blockIdx.y;
    int idx = b * Nn + n;

    int typ = types[idx];
    int p   = cpos[idx];
    int v0  = vals[2 * idx];
    int v1  = vals[2 * idx + 1];

    const float4* te4 = (const float4*)te;
    const float4* pp4 = (const float4*)pos;
    const float4* tk4 = (const float4*)tok;

    float4 e  = te4[typ * 64 + t];
    float4 pv = pp4[(size_t)p * 64 + t];
    float4 t0 = tk4[(size_t)v0 * 64 + t];
    float4 t1 = tk4[(size_t)v1 * 64 + t];

    float4 o;
    o.x = 4.f * e.x + 0.25f * pv.x + 2.f * (t0.x + t1.x);
    o.y = 4.f * e.y + 0.25f * pv.y + 2.f * (t0.y + t1.y);
    o.z = 4.f * e.z + 0.25f * pv.z + 2.f * (t0.z + t1.z);
    o.w = 4.f * e.w + 0.25f * pv.w + 2.f * (t0.w + t1.w);

    ((float4*)out)[((size_t)n * Bb + b) * 128 + t] = o;
}

// ---------------------------------------------------------------------------
// GRU scan: 16 clusters x 8 CTAs; cluster owns batches [4c,4c+4); CTA rank r
// owns H-cols [32r,32r+32) of all 3 gates (96 W_hh rows in SMEM, f32).
// History rows live in out[:, :, 256:512]; parents prefetched one step ahead.
// ---------------------------------------------------------------------------
__global__ void __cluster_dims__(8, 1, 1) __launch_bounds__(384, 1)
scan_kernel(const int* __restrict__ types, const int* __restrict__ cpos,
            const int* __restrict__ lpi,
            const float* __restrict__ bih_g, const float* __restrict__ bhh_g,
            const float* __restrict__ whh, float* __restrict__ out)
{
    extern __shared__ float sm[];
    const int tid  = threadIdx.x;
    const int rank = blockIdx.x & 7;
    const int cid  = blockIdx.x >> 3;

    // matvec mapping: 96 gate-rows x 4 batches
    const int j    = tid >> 2;
    const int bl   = tid & 3;
    const int gb   = cid * 4 + bl;
    const int grow = ((j >> 5) << 8) + (rank << 5) + (j & 31);
    const float bih = bih_g[grow];
    const float bhh = bhh_g[grow];

    // gather mapping (tid < 256): 4 batches x 64 float4 chunks
    const int b2  = (tid >> 6) & 3;
    const int kc2 = tid & 63;
    const int gb2 = cid * 4 + b2;

    float4* WS4 = (float4*)sm;
    float4* HS4 = (float4*)(sm + HS_F);
    float*  GH  = sm + GH_F;
    float*  GI  = sm + GI_F;

    // prologue: load W_hh slice (padded pitch 65 float4), zero h buffers, gi[0]
    const float4* Wg4 = (const float4*)whh;
    for (int idx = tid; idx < 96 * 64; idx += 384) {
        int jj = idx >> 6, kc = idx & 63;
        int gr = ((jj >> 5) << 8) + (rank << 5) + (jj & 31);
        WS4[jj * 65 + kc] = Wg4[gr * 64 + kc];
    }
    for (int idx = tid; idx < 520; idx += 384) HS4[idx] = make_float4(0.f, 0.f, 0.f, 0.f);
    {
        int t0 = types[gb * Nn], p0 = cpos[gb * Nn];
        GI[tid] = fmaf(4.f, g_TE[t0 * G3H + grow],
                  fmaf(0.25f, g_POS[p0 * G3H + grow], bih));
    }
    __syncthreads();

    const float4* outR = (const float4*)out;
    int cur = 0;
    for (int i = 0; i < Nn; i++) {
        const int nxt = cur ^ 1;

        // matvec for step i using prefetched h (valid unless lpi[i]==i-1)
        float a0 = bhh, a1 = 0.f, a2 = 0.f, a3 = 0.f;
        {
            const float4* wr = WS4 + j * 65;
            const float4* hp = HS4 + cur * 260 + bl * 65;
#pragma unroll 16
            for (int kc = 0; kc < 64; kc++) {
                float4 w = wr[kc], h = hp[kc];
                a0 = fmaf(w.x, h.x, a0); a1 = fmaf(w.y, h.y, a1);
                a2 = fmaf(w.z, h.z, a2); a3 = fmaf(w.w, h.w, a3);
            }
        }

        if (i > 0) {
            // barrier latency hidden behind the matvec above
            asm volatile("barrier.cluster.wait.aligned;" ::: "memory");
            // rare deferred parent (lpi[i] == i-1): load fresh row, redo dot
            if (tid < 256 && lpi[gb2 * Nn + i] == i - 1)
                HS4[cur * 260 + b2 * 65 + kc2] =
                    __ldcg(outR + ((size_t)(i - 1) * Bb + gb2) * 128 + 64 + kc2);
            __syncthreads();
            if (lpi[gb * Nn + i] == i - 1) {
                const float4* wr = WS4 + j * 65;
                const float4* hp = HS4 + cur * 260 + bl * 65;
                a0 = bhh; a1 = 0.f; a2 = 0.f; a3 = 0.f;
#pragma unroll 16
                for (int kc = 0; kc < 64; kc++) {
                    float4 w = wr[kc], h = hp[kc];
                    a0 = fmaf(w.x, h.x, a0); a1 = fmaf(w.y, h.y, a1);
                    a2 = fmaf(w.z, h.z, a2); a3 = fmaf(w.w, h.w, a3);
                }
            }
        }

        // prefetch parent h + input gates for step i+1
        float gin = 0.f;
        if (i + 1 < Nn) {
            if (tid < 256) {
                int nl = lpi[gb2 * Nn + i + 1];
                if (nl < i)
                    HS4[nxt * 260 + b2 * 65 + kc2] =
                        __ldcg(outR + ((size_t)nl * Bb + gb2) * 128 + 64 + kc2);
            }
            int tn = types[gb * Nn + i + 1], pn = cpos[gb * Nn + i + 1];
            gin = fmaf(4.f, g_TE[tn * G3H + grow],
                  fmaf(0.25f, g_POS[pn * G3H + grow], bih));
        }

        GH[tid] = (a0 + a1) + (a2 + a3);
        GI[nxt * 384 + tid] = gin;
        __syncthreads();

        // gate combine + hidden write (128 threads: 32 cols x 4 batches)
        if (tid < 128) {
            int q = tid >> 2, bc = tid & 3;
            const float* gic = GI + cur * 384;
            float ghr = GH[q * 4 + bc],        gir  = gic[q * 4 + bc];
            float ghz = GH[(32 + q) * 4 + bc], giz  = gic[(32 + q) * 4 + bc];
            float ghn = GH[(64 + q) * 4 + bc], ginn = gic[(64 + q) * 4 + bc];
            float r  = 1.f / (1.f + __expf(-(gir + ghr)));
            float z  = 1.f / (1.f + __expf(-(giz + ghz)));
            float nn = tanhf(ginn + r * ghn);
            float hp = sm[HS_F + cur * 1040 + bc * 260 + (rank << 5) + q];
            float h  = (1.f - z) * nn + z * hp;
            out[((size_t)i * Bb + (cid * 4 + bc)) * 512 + 256 + (rank << 5) + q] = h;
        }

        if (i < Nn - 1)
            asm volatile("barrier.cluster.arrive.aligned;" ::: "memory");
        cur = nxt;
    }
}

// ---------------------------------------------------------------------------
extern "C" void kernel_launch(void* const* d_in, const int* in_sizes, int n_in,
                              void* d_out, int out_size)
{
    const int*   types = (const int*)d_in[0];
    const int*   vals  = (const int*)d_in[1];
    /* d_in[2] = node_val_offsets: fixed arange*2, unused */
    const int*   lpi   = (const int*)d_in[3];
    const int*   cposi = (const int*)d_in[4];
    const float* te    = (const float*)d_in[5];
    const float* pos   = (const float*)d_in[6];
    const float* tok   = (const float*)d_in[7];
    const float* wih   = (const float*)d_in[8];
    const float* whh   = (const float*)d_in[9];
    const float* bih   = (const float*)d_in[10];
    const float* bhh   = (const float*)d_in[11];
    float* out = (float*)d_out;
    (void)in_sizes; (void)n_in; (void)out_size;

    proj_kernel<<<dim3(38, 6), 128>>>(te, wih, 300, 0);
    proj_kernel<<<dim3(125, 6), 128>>>(pos, wih, 1000, 1);
    embed_kernel<<<dim3(256, 64), 256>>>(types, vals, cposi, te, pos, tok, out);

    cudaFuncSetAttribute(scan_kernel, cudaFuncAttributeMaxDynamicSharedMemorySize, SMEMB);
    scan_kernel<<<128, 384, SMEMB>>>(types, cposi, lpi, bih, bhh, whh, out);
}

// round 7
// speedup vs baseline: 1.1278x; 1.1278x over previous
#include <cuda_runtime.h>
#include <cuda_bf16.h>

#define Bb   64
#define Nn   1024
#define G3H  768

// Precomputed input-gate tables (allocation-free scratch)
__device__ float g_TE[300 * G3H];    // type_emb @ w_ih^T
__device__ float g_POS[1000 * G3H];  // pos_table @ w_ih^T

// ---------------------------------------------------------------------------
// proj: out[r][j] = dot(A[r, 0:256], W[j, 0:256]);  grid (ceil(rows/8), 6), 128 thr
// ---------------------------------------------------------------------------
__global__ void proj_kernel(const float* __restrict__ A, const float* __restrict__ W,
                            int rows, int which)
{
    __shared__ float As[8][256];
    float* outp = which ? g_POS : g_TE;
    int r0 = blockIdx.x * 8;
    int j  = blockIdx.y * 128 + threadIdx.x;

    for (int idx = threadIdx.x; idx < 2048; idx += 128) {
        int rr = idx >> 8, kk = idx & 255;
        As[rr][kk] = (r0 + rr < rows) ? A[(r0 + rr) * 256 + kk] : 0.f;
    }
    __syncthreads();

    float acc[8] = {0, 0, 0, 0, 0, 0, 0, 0};
    const float4* W4 = (const float4*)W + j * 64;
#pragma unroll 8
    for (int kc = 0; kc < 64; kc++) {
        float4 w = W4[kc];
#pragma unroll
        for (int rr = 0; rr < 8; rr++) {
            acc[rr] = fmaf(w.x, As[rr][kc * 4 + 0], acc[rr]);
            acc[rr] = fmaf(w.y, As[rr][kc * 4 + 1], acc[rr]);
            acc[rr] = fmaf(w.z, As[rr][kc * 4 + 2], acc[rr]);
            acc[rr] = fmaf(w.w, As[rr][kc * 4 + 3], acc[rr]);
        }
    }
#pragma unroll
    for (int rr = 0; rr < 8; rr++)
        if (r0 + rr < rows) outp[(r0 + rr) * G3H + j] = acc[rr];
}

// ---------------------------------------------------------------------------
// embedding half: out[n][b][0:256] = 4*te[t] + 0.25*pos[p] + 2*(tok[v0]+tok[v1])
// ---------------------------------------------------------------------------
__global__ void embed_kernel(const int* __restrict__ types, const int* __restrict__ vals,
                             const int* __restrict__ cpos,
                             const float* __restrict__ te, const float* __restrict__ pos,
                             const float* __restrict__ tok, float* __restrict__ out)
{
    int sub = threadIdx.x >> 6;
    int t   = threadIdx.x & 63;
    int n   = blockIdx.x * 4 + sub;
    int b   = blockIdx.y;
    int idx = b * Nn + n;

    int typ = types[idx];
    int p   = cpos[idx];
    int v0  = vals[2 * idx];
    int v1  = vals[2 * idx + 1];

    const float4* te4 = (const float4*)te;
    const float4* pp4 = (const float4*)pos;
    const float4* tk4 = (const float4*)tok;

    float4 e  = te4[typ * 64 + t];
    float4 pv = pp4[(size_t)p * 64 + t];
    float4 t0 = tk4[(size_t)v0 * 64 + t];
    float4 t1 = tk4[(size_t)v1 * 64 + t];

    float4 o;
    o.x = 4.f * e.x + 0.25f * pv.x + 2.f * (t0.x + t1.x);
    o.y = 4.f * e.y + 0.25f * pv.y + 2.f * (t0.y + t1.y);
    o.z = 4.f * e.z + 0.25f * pv.z + 2.f * (t0.z + t1.z);
    o.w = 4.f * e.w + 0.25f * pv.w + 2.f * (t0.w + t1.w);

    ((float4*)out)[((size_t)n * Bb + b) * 128 + t] = o;
}

// ---------------------------------------------------------------------------
// packed f32x2 helpers (exact f32 math, half the FFMA instruction count)
// ---------------------------------------------------------------------------
__device__ __forceinline__ void ffma2(unsigned long long& d,
                                      unsigned long long a, unsigned long long b)
{
    asm("fma.rn.f32x2 %0, %1, %2, %0;" : "+l"(d) : "l"(a), "l"(b));
}
__device__ __forceinline__ float2 unpk(unsigned long long v)
{
    float2 r; asm("mov.b64 {%0, %1}, %2;" : "=f"(r.x), "=f"(r.y) : "l"(v)); return r;
}

// ---------------------------------------------------------------------------
// GRU scan: 16 independent clusters x 8 CTAs; cluster c owns batches [4c,4c+4).
// CTA rank r owns H-cols [32r,32r+32) of all 3 gates (96 gate-rows).
// Thread mapping: tid = j*4 + q  (j = local gate-row 0..95, q = K-quarter 0..3).
// W_hh slice lives in REGISTERS (64 floats/thread). h vectors in SMEM with
// quarter-pitch padding so warp loads are broadcast + conflict-free.
// History rows live in out[:, :, 256:512]; parents prefetched one step ahead;
// stale-parent (lpi == i-1) batches flagged and redone after the barrier.
// ---------------------------------------------------------------------------
__global__ void __cluster_dims__(8, 1, 1) __launch_bounds__(384, 1)
scan_kernel(const int* __restrict__ types, const int* __restrict__ cpos,
            const int* __restrict__ lpi,
            const float* __restrict__ bih_g, const float* __restrict__ bhh_g,
            const float* __restrict__ whh, float* __restrict__ out)
{
    // h buffers: 2 x 4 batches x (4 quarters * 17 float4) = 544 float4
    __shared__ float4 HS4[544];
    __shared__ float  GH[384];       // gh staging: 96 rows x 4 batches
    __shared__ float  GI[768];       // gi double buffer: 2 x 384
    __shared__ int    sFlag[8];      // 2 x 4 stale-parent flags

    const int tid  = threadIdx.x;
    const int rank = blockIdx.x & 7;
    const int cid  = blockIdx.x >> 3;

    const int j    = tid >> 2;                                  // 0..95
    const int q    = tid & 3;                                   // K-quarter
    const int grow = ((j >> 5) << 8) + (rank << 5) + (j & 31);  // global gate row
    const int gbq  = cid * 4 + q;                               // batch for gi duty
    const float bih = bih_g[grow];
    const float bhh = bhh_g[grow];

    // gather mapping (tid < 256): 4 batches x 64 float4 chunks
    const int b2  = (tid >> 6) & 3;
    const int kc2 = tid & 63;
    const int gb2 = cid * 4 + b2;
    const int hslot2 = b2 * 68 + (kc2 >> 4) * 17 + (kc2 & 15);

    // ---- W_hh chunk -> registers (64 floats = 16 ulonglong2) ----
    ulonglong2 Wreg[16];
    {
        const ulonglong2* wp = (const ulonglong2*)(whh + (size_t)grow * 256 + q * 64);
#pragma unroll
        for (int t = 0; t < 16; t++) Wreg[t] = wp[t];
    }

    // zero h buffers, gi for step 0
    for (int idx = tid; idx < 544; idx += 384) HS4[idx] = make_float4(0.f, 0.f, 0.f, 0.f);
    {
        int t0 = types[gbq * Nn], p0 = cpos[gbq * Nn];
        GI[tid] = fmaf(4.f, g_TE[(size_t)t0 * G3H + grow],
                  fmaf(0.25f, g_POS[(size_t)p0 * G3H + grow], bih));
    }
    __syncthreads();

    const float4* outR = (const float4*)out;
    int cur = 0;
    for (int i = 0; i < Nn; i++) {
        const int nxt = cur ^ 1;

        // ---- matvec partials over this thread's K-quarter, all 4 batches ----
        unsigned long long acc[4][2];
        float s[4];
#pragma unroll
        for (int bl = 0; bl < 4; bl++) { acc[bl][0] = 0ull; acc[bl][1] = 0ull; }
#pragma unroll
        for (int bl = 0; bl < 4; bl++) {
            const ulonglong2* hb = (const ulonglong2*)(HS4 + cur * 272 + bl * 68 + q * 17);
#pragma unroll
            for (int t = 0; t < 16; t++) {
                ulonglong2 h2 = hb[t];
                ffma2(acc[bl][0], Wreg[t].x, h2.x);
                ffma2(acc[bl][1], Wreg[t].y, h2.y);
            }
        }
#pragma unroll
        for (int bl = 0; bl < 4; bl++) {
            float2 u = unpk(acc[bl][0]), v = unpk(acc[bl][1]);
            float sv = (u.x + u.y) + (v.x + v.y);
            sv += __shfl_xor_sync(0xffffffffu, sv, 1);
            sv += __shfl_xor_sync(0xffffffffu, sv, 2);
            s[bl] = sv;
        }

        if (i > 0) {
            // barrier latency largely hidden behind the matvec above
            asm volatile("barrier.cluster.wait.aligned;" ::: "memory");
            int fl[4];
#pragma unroll
            for (int bl = 0; bl < 4; bl++) fl[bl] = sFlag[cur * 4 + bl];
            // stale parent (lpi[i] == i-1): fetch fresh row i-1 for flagged batches
            if (tid < 256 && fl[b2])
                HS4[cur * 272 + hslot2] =
                    __ldcg(outR + ((size_t)(i - 1) * Bb + gb2) * 128 + 64 + kc2);
            __syncthreads();
#pragma unroll
            for (int bl = 0; bl < 4; bl++) {
                if (fl[bl]) {   // uniform across CTA
                    unsigned long long a0 = 0ull, a1 = 0ull;
                    const ulonglong2* hb =
                        (const ulonglong2*)(HS4 + cur * 272 + bl * 68 + q * 17);
#pragma unroll
                    for (int t = 0; t < 16; t++) {
                        ulonglong2 h2 = hb[t];
                        ffma2(a0, Wreg[t].x, h2.x);
                        ffma2(a1, Wreg[t].y, h2.y);
                    }
                    float2 u = unpk(a0), v = unpk(a1);
                    float sv = (u.x + u.y) + (v.x + v.y);
                    sv += __shfl_xor_sync(0xffffffffu, sv, 1);
                    sv += __shfl_xor_sync(0xffffffffu, sv, 2);
                    s[bl] = sv;
                }
            }
        }

        // ---- prefetch parent h + input gates for step i+1 ----
        float gin = 0.f;
        if (i + 1 < Nn) {
            if (tid < 256) {
                int nl = lpi[gb2 * Nn + i + 1];           // nl <= i
                if (kc2 == 0) sFlag[nxt * 4 + b2] = (nl == i);
                if (nl < i)
                    HS4[nxt * 272 + hslot2] =
                        __ldcg(outR + ((size_t)nl * Bb + gb2) * 128 + 64 + kc2);
            }
            int tn = types[gbq * Nn + i + 1], pn = cpos[gbq * Nn + i + 1];
            gin = fmaf(4.f, g_TE[(size_t)tn * G3H + grow],
                  fmaf(0.25f, g_POS[(size_t)pn * G3H + grow], bih));
        }

        GH[tid] = s[q] + bhh;            // gh[row j][batch q]
        GI[nxt * 384 + tid] = gin;
        __syncthreads();

        // ---- gate combine + hidden write (128 threads: 32 cols x 4 batches) ----
        if (tid < 128) {
            int qc = tid >> 2, bc = tid & 3;
            const float* gic = GI + cur * 384;
            float ghr = GH[(qc)      * 4 + bc], gir  = gic[(qc)      * 4 + bc];
            float ghz = GH[(32 + qc) * 4 + bc], giz  = gic[(32 + qc) * 4 + bc];
            float ghn = GH[(64 + qc) * 4 + bc], ginn = gic[(64 + qc) * 4 + bc];
            float r = 1.f / (1.f + __expf(-(gir + ghr)));
            float z = 1.f / (1.f + __expf(-(giz + ghz)));
            float narg = ginn + r * ghn;
            float nn; asm("tanh.approx.f32 %0, %1;" : "=f"(nn) : "f"(narg));
            int c = (rank << 5) + qc;
            float hp = ((const float*)HS4)[(cur * 272 + bc * 68 + (c >> 6) * 17 +
                                            ((c >> 2) & 15)) * 4 + (c & 3)];
            float h = (1.f - z) * nn + z * hp;
            out[((size_t)i * Bb + (cid * 4 + bc)) * 512 + 256 + c] = h;
        }

        if (i < Nn - 1)
            asm volatile("barrier.cluster.arrive.aligned;" ::: "memory");
        cur = nxt;
    }
}

// ---------------------------------------------------------------------------
extern "C" void kernel_launch(void* const* d_in, const int* in_sizes, int n_in,
                              void* d_out, int out_size)
{
    const int*   types = (const int*)d_in[0];
    const int*   vals  = (const int*)d_in[1];
    /* d_in[2] = node_val_offsets: fixed arange*2, unused */
    const int*   lpi   = (const int*)d_in[3];
    const int*   cposi = (const int*)d_in[4];
    const float* te    = (const float*)d_in[5];
    const float* pos   = (const float*)d_in[6];
    const float* tok   = (const float*)d_in[7];
    const float* wih   = (const float*)d_in[8];
    const float* whh   = (const float*)d_in[9];
    const float* bih   = (const float*)d_in[10];
    const float* bhh   = (const float*)d_in[11];
    float* out = (float*)d_out;
    (void)in_sizes; (void)n_in; (void)out_size;

    proj_kernel<<<dim3(38, 6), 128>>>(te, wih, 300, 0);
    proj_kernel<<<dim3(125, 6), 128>>>(pos, wih, 1000, 1);
    embed_kernel<<<dim3(256, 64), 256>>>(types, vals, cposi, te, pos, tok, out);
    scan_kernel<<<128, 384>>>(types, cposi, lpi, bih, bhh, whh, out);
}

// round 8
// speedup vs baseline: 1.4739x; 1.3069x over previous
#include <cuda_runtime.h>
#include <cuda_bf16.h>

#define Bb   64
#define Nn   1024
#define G3H  768

// Precomputed input-gate tables (allocation-free scratch)
__device__ float g_TE[300 * G3H];    // type_emb @ w_ih^T
__device__ float g_POS[1000 * G3H];  // pos_table @ w_ih^T

// ---------------------------------------------------------------------------
// proj: out[r][j] = dot(A[r, 0:256], W[j, 0:256]);  grid (ceil(rows/8), 6), 128 thr
// ---------------------------------------------------------------------------
__global__ void proj_kernel(const float* __restrict__ A, const float* __restrict__ W,
                            int rows, int which)
{
    __shared__ float As[8][256];
    float* outp = which ? g_POS : g_TE;
    int r0 = blockIdx.x * 8;
    int j  = blockIdx.y * 128 + threadIdx.x;

    for (int idx = threadIdx.x; idx < 2048; idx += 128) {
        int rr = idx >> 8, kk = idx & 255;
        As[rr][kk] = (r0 + rr < rows) ? A[(r0 + rr) * 256 + kk] : 0.f;
    }
    __syncthreads();

    float acc[8] = {0, 0, 0, 0, 0, 0, 0, 0};
    const float4* W4 = (const float4*)W + j * 64;
#pragma unroll 8
    for (int kc = 0; kc < 64; kc++) {
        float4 w = W4[kc];
#pragma unroll
        for (int rr = 0; rr < 8; rr++) {
            acc[rr] = fmaf(w.x, As[rr][kc * 4 + 0], acc[rr]);
            acc[rr] = fmaf(w.y, As[rr][kc * 4 + 1], acc[rr]);
            acc[rr] = fmaf(w.z, As[rr][kc * 4 + 2], acc[rr]);
            acc[rr] = fmaf(w.w, As[rr][kc * 4 + 3], acc[rr]);
        }
    }
#pragma unroll
    for (int rr = 0; rr < 8; rr++)
        if (r0 + rr < rows) outp[(r0 + rr) * G3H + j] = acc[rr];
}

// ---------------------------------------------------------------------------
// embedding half: out[n][b][0:256] = 4*te[t] + 0.25*pos[p] + 2*(tok[v0]+tok[v1])
// ---------------------------------------------------------------------------
__global__ void embed_kernel(const int* __restrict__ types, const int* __restrict__ vals,
                             const int* __restrict__ cpos,
                             const float* __restrict__ te, const float* __restrict__ pos,
                             const float* __restrict__ tok, float* __restrict__ out)
{
    int sub = threadIdx.x >> 6;
    int t   = threadIdx.x & 63;
    int n   = blockIdx.x * 4 + sub;
    int b   = blockIdx.y;
    int idx = b * Nn + n;

    int typ = types[idx];
    int p   = cpos[idx];
    int v0  = vals[2 * idx];
    int v1  = vals[2 * idx + 1];

    const float4* te4 = (const float4*)te;
    const float4* pp4 = (const float4*)pos;
    const float4* tk4 = (const float4*)tok;

    float4 e  = te4[typ * 64 + t];
    float4 pv = pp4[(size_t)p * 64 + t];
    float4 t0 = tk4[(size_t)v0 * 64 + t];
    float4 t1 = tk4[(size_t)v1 * 64 + t];

    float4 o;
    o.x = 4.f * e.x + 0.25f * pv.x + 2.f * (t0.x + t1.x);
    o.y = 4.f * e.y + 0.25f * pv.y + 2.f * (t0.y + t1.y);
    o.z = 4.f * e.z + 0.25f * pv.z + 2.f * (t0.z + t1.z);
    o.w = 4.f * e.w + 0.25f * pv.w + 2.f * (t0.w + t1.w);

    ((float4*)out)[((size_t)n * Bb + b) * 128 + t] = o;
}

// ---------------------------------------------------------------------------
// packed f32x2 helpers (exact f32 math)
// ---------------------------------------------------------------------------
__device__ __forceinline__ void ffma2(unsigned long long& d,
                                      unsigned long long a, unsigned long long b)
{
    asm("fma.rn.f32x2 %0, %1, %2, %0;" : "+l"(d) : "l"(a), "l"(b));
}
__device__ __forceinline__ float2 unpk(unsigned long long v)
{
    float2 r; asm("mov.b64 {%0, %1}, %2;" : "=f"(r.x), "=f"(r.y) : "l"(v)); return r;
}

// ---------------------------------------------------------------------------
// GRU scan: 16 independent clusters x 8 CTAs; cluster c owns batches [4c,4c+4).
// CTA rank r owns H-cols [32r,32r+32) of all 3 gates (96 gate-rows).
// tid = j*4 + q (j = gate-row 0..95, q = K-quarter). W_hh in registers.
// ALL index streams staged in SMEM; parent rows + gi table rows are issued at
// the top of step i and consumed at its end (latency hidden by the step body).
// ---------------------------------------------------------------------------
__global__ void __cluster_dims__(8, 1, 1) __launch_bounds__(384, 1)
scan_kernel(const int* __restrict__ types, const int* __restrict__ cpos,
            const int* __restrict__ lpi,
            const float* __restrict__ bih_g, const float* __restrict__ bhh_g,
            const float* __restrict__ whh, float* __restrict__ out)
{
    __shared__ int    sLpi[4096];    // 4 batches x 1024
    __shared__ int    sTP[4096];     // packed (type<<16)|cpos
    __shared__ float4 HS4[544];      // 2 x 4 batches x (4*17) float4, padded
    __shared__ float  GH[384];       // gh staging
    __shared__ float  GI[768];       // gi double buffer

    const int tid  = threadIdx.x;
    const int rank = blockIdx.x & 7;
    const int cid  = blockIdx.x >> 3;

    const int j    = tid >> 2;
    const int q    = tid & 3;
    const int grow = ((j >> 5) << 8) + (rank << 5) + (j & 31);
    const float bih = bih_g[grow];
    const float bhh = bhh_g[grow];

    // gather mapping (tid < 256): 4 batches x 64 float4 chunks
    const int b2  = (tid >> 6) & 3;
    const int kc2 = tid & 63;
    const int gb2 = cid * 4 + b2;
    const int hslot2 = b2 * 68 + (kc2 >> 4) * 17 + (kc2 & 15);

    // W_hh chunk -> registers (64 floats = 16 ulonglong2)
    ulonglong2 Wreg[16];
    {
        const ulonglong2* wp = (const ulonglong2*)(whh + (size_t)grow * 256 + q * 64);
#pragma unroll
        for (int t = 0; t < 16; t++) Wreg[t] = wp[t];
    }

    // stage all index streams for this cluster's 4 batches
    for (int idx = tid; idx < 4096; idx += 384) {
        int b = idx >> 10, k = idx & 1023;
        int g = (cid * 4 + b) * Nn + k;
        sLpi[idx] = lpi[g];
        sTP[idx]  = (types[g] << 16) | cpos[g];
    }
    for (int idx = tid; idx < 544; idx += 384) HS4[idx] = make_float4(0.f, 0.f, 0.f, 0.f);
    __syncthreads();
    {
        int tp = sTP[q * 1024];
        GI[tid] = fmaf(4.f, g_TE[(size_t)(unsigned)(tp >> 16) * G3H + grow],
                  fmaf(0.25f, g_POS[(size_t)(tp & 0xffff) * G3H + grow], bih));
    }
    __syncthreads();

    const float4* outR = (const float4*)out;
    int cur = 0;
    for (int i = 0; i < Nn; i++) {
        const int nxt = cur ^ 1;

        // ---- early issue of long-latency loads for step i+1 ----
        float4 pf = make_float4(0.f, 0.f, 0.f, 0.f);
        int pl = -1;
        float eT = 0.f, eP = 0.f;
        if (i + 1 < Nn) {
            if (tid < 256) {
                pl = sLpi[b2 * 1024 + i + 1];          // parent of step i+1 (<= i)
                if (pl <= i - 2)                        // visible pre-wait
                    pf = __ldcg(outR + ((size_t)pl * Bb + gb2) * 128 + 64 + kc2);
            }
            int tp = sTP[q * 1024 + i + 1];
            eT = __ldg(g_TE  + (size_t)(unsigned)(tp >> 16) * G3H + grow);
            eP = __ldg(g_POS + (size_t)(tp & 0xffff) * G3H + grow);
        }

        // ---- matvec partials on HS4[cur] (all 4 batches) ----
        float s[4];
        {
            unsigned long long acc[4][2];
#pragma unroll
            for (int bl = 0; bl < 4; bl++) { acc[bl][0] = 0ull; acc[bl][1] = 0ull; }
#pragma unroll
            for (int bl = 0; bl < 4; bl++) {
                const ulonglong2* hb =
                    (const ulonglong2*)(HS4 + cur * 272 + bl * 68 + q * 17);
#pragma unroll
                for (int t = 0; t < 16; t++) {
                    ulonglong2 h2 = hb[t];
                    ffma2(acc[bl][0], Wreg[t].x, h2.x);
                    ffma2(acc[bl][1], Wreg[t].y, h2.y);
                }
            }
#pragma unroll
            for (int bl = 0; bl < 4; bl++) {
                float2 u = unpk(acc[bl][0]), v = unpk(acc[bl][1]);
                float sv = (u.x + u.y) + (v.x + v.y);
                sv += __shfl_xor_sync(0xffffffffu, sv, 1);
                sv += __shfl_xor_sync(0xffffffffu, sv, 2);
                s[bl] = sv;
            }
        }

        if (i > 0) {
            // barrier latency largely hidden behind the matvec above
            asm volatile("barrier.cluster.wait.aligned;" ::: "memory");

            // stale parents for CURRENT step (lpi[i] == i-1): rare uniform redo
            int mask = 0;
#pragma unroll
            for (int bl = 0; bl < 4; bl++)
                mask |= (sLpi[bl * 1024 + i] == i - 1) ? (1 << bl) : 0;
            if (mask) {
                if (tid < 256 && ((mask >> b2) & 1))
                    HS4[cur * 272 + hslot2] =
                        __ldcg(outR + ((size_t)(i - 1) * Bb + gb2) * 128 + 64 + kc2);
                __syncthreads();
                unsigned long long acc[4][2];
#pragma unroll
                for (int bl = 0; bl < 4; bl++) { acc[bl][0] = 0ull; acc[bl][1] = 0ull; }
#pragma unroll
                for (int bl = 0; bl < 4; bl++) {
                    const ulonglong2* hb =
                        (const ulonglong2*)(HS4 + cur * 272 + bl * 68 + q * 17);
#pragma unroll
                    for (int t = 0; t < 16; t++) {
                        ulonglong2 h2 = hb[t];
                        ffma2(acc[bl][0], Wreg[t].x, h2.x);
                        ffma2(acc[bl][1], Wreg[t].y, h2.y);
                    }
                }
#pragma unroll
                for (int bl = 0; bl < 4; bl++) {
                    float2 u = unpk(acc[bl][0]), v = unpk(acc[bl][1]);
                    float sv = (u.x + u.y) + (v.x + v.y);
                    sv += __shfl_xor_sync(0xffffffffu, sv, 1);
                    sv += __shfl_xor_sync(0xffffffffu, sv, 2);
                    s[bl] = sv;
                }
            }

            // deferred near-parent fetch for step i+1 (row i-1 now visible)
            if (tid < 256 && pl == i - 1)
                pf = __ldcg(outR + ((size_t)(i - 1) * Bb + gb2) * 128 + 64 + kc2);
        }

        // ---- stage data for step i+1 ----
        if (tid < 256 && pl >= 0 && pl < i)
            HS4[nxt * 272 + hslot2] = pf;        // pl == i handled as stale next step
        GH[tid] = s[q] + bhh;
        if (i + 1 < Nn)
            GI[nxt * 384 + tid] = fmaf(4.f, eT, fmaf(0.25f, eP, bih));
        __syncthreads();

        // ---- gate combine + hidden write (tid<128: warp = one batch) ----
        if (tid < 128) {
            int bc = tid >> 5, qc = tid & 31;
            const float* gic = GI + cur * 384;
            float ghr = GH[(qc)      * 4 + bc], gir  = gic[(qc)      * 4 + bc];
            float ghz = GH[(32 + qc) * 4 + bc], giz  = gic[(32 + qc) * 4 + bc];
            float ghn = GH[(64 + qc) * 4 + bc], ginn = gic[(64 + qc) * 4 + bc];
            float r = 1.f / (1.f + __expf(-(gir + ghr)));
            float z = 1.f / (1.f + __expf(-(giz + ghz)));
            float narg = ginn + r * ghn;
            float nn; asm("tanh.approx.f32 %0, %1;" : "=f"(nn) : "f"(narg));
            int c = (rank << 5) + qc;
            float hp = ((const float*)HS4)[(cur * 272 + bc * 68 + (c >> 6) * 17 +
                                            ((c >> 2) & 15)) * 4 + (c & 3)];
            float h = (1.f - z) * nn + z * hp;
            __stcg(&out[((size_t)i * Bb + (cid * 4 + bc)) * 512 + 256 + c], h);
        }

        if (i < Nn - 1)
            asm volatile("barrier.cluster.arrive.aligned;" ::: "memory");
        cur = nxt;
    }
}

// ---------------------------------------------------------------------------
extern "C" void kernel_launch(void* const* d_in, const int* in_sizes, int n_in,
                              void* d_out, int out_size)
{
    const int*   types = (const int*)d_in[0];
    const int*   vals  = (const int*)d_in[1];
    /* d_in[2] = node_val_offsets: fixed arange*2, unused */
    const int*   lpi   = (const int*)d_in[3];
    const int*   cposi = (const int*)d_in[4];
    const float* te    = (const float*)d_in[5];
    const float* pos   = (const float*)d_in[6];
    const float* tok   = (const float*)d_in[7];
    const float* wih   = (const float*)d_in[8];
    const float* whh   = (const float*)d_in[9];
    const float* bih   = (const float*)d_in[10];
    const float* bhh   = (const float*)d_in[11];
    float* out = (float*)d_out;
    (void)in_sizes; (void)n_in; (void)out_size;

    proj_kernel<<<dim3(38, 6), 128>>>(te, wih, 300, 0);
    proj_kernel<<<dim3(125, 6), 128>>>(pos, wih, 1000, 1);
    embed_kernel<<<dim3(256, 64), 256>>>(types, vals, cposi, te, pos, tok, out);
    scan_kernel<<<128, 384>>>(types, cposi, lpi, bih, bhh, whh, out);
}